// round 9
// baseline (speedup 1.0000x reference)
#include <cuda_runtime.h>
#include <cuda_bf16.h>

// ChamferDistance: B=4, C=3, N=M=8192, fp32 -> scalar.
// t = x.y - 0.5||y||^2; per-query max; t_full = max - hx <= 0 -> raw-bit atomicMin.
// R9: back to the empirically fastest shape (THREADS=128, QPT=4, big TCHUNK),
//     unroll 4 for ILP, fused last-block reduce. FFMA2 issue cost ~3cyc is the
//     structural floor; this round maximizes schedule quality around it.

#define NPTS    8192
#define NBATCH  4
#define THREADS 128
#define QPT     4
#define QTILE   (THREADS * QPT)          // 512 queries per block
#define NQT     (NPTS / QTILE)           // 16
#define TCHUNK  256                      // targets per block
#define NTC     (NPTS / TCHUNK)          // 32
#define NBLOCKS (2 * NBATCH * NQT * NTC) // 4096
#define NKEYS   (2 * NBATCH * NPTS)      // 65536
#define NEG_INF (-3.402823466e38f)

__device__ unsigned g_key[NKEYS];   // raw bits of t_full (<=0), merged via umin
__device__ unsigned g_count;

typedef unsigned long long u64;

__device__ __forceinline__ u64 fma2(u64 a, u64 b, u64 c) {
    u64 d;
    asm("fma.rn.f32x2 %0, %1, %2, %3;" : "=l"(d) : "l"(a), "l"(b), "l"(c));
    return d;
}
__device__ __forceinline__ u64 pack2(float x) {
    u64 d;
    asm("mov.b64 %0, {%1, %1};" : "=l"(d) : "f"(x));
    return d;
}
__device__ __forceinline__ void unpack2(u64 v, float& lo, float& hi) {
    asm("mov.b64 {%0, %1}, %2;" : "=f"(lo), "=f"(hi) : "l"(v));
}
__device__ __forceinline__ void lds_v2u64(unsigned addr, u64& a, u64& b) {
    asm volatile("ld.shared.v2.u64 {%0, %1}, [%2];" : "=l"(a), "=l"(b) : "r"(addr));
}

__global__ void chamfer_init_kernel() {
    int i = blockIdx.x * blockDim.x + threadIdx.x;
    g_key[i] = 0xFFFFFFFFu;   // umin identity
    if (i == 0) g_count = 0u;
}

__global__ __launch_bounds__(THREADS)
void chamfer_main_kernel(const float* __restrict__ pred,
                         const float* __restrict__ targ,
                         float* __restrict__ out) {
    const int u   = blockIdx.x;
    const int tc  = u & (NTC - 1);
    const int qt  = (u >> 5) & (NQT - 1);
    const int b   = (u >> 9) & (NBATCH - 1);
    const int dir = u >> 11;

    const float* __restrict__ X = (dir ? targ : pred) + (size_t)b * 3 * NPTS;  // queries
    const float* __restrict__ Y = (dir ? pred : targ) + (size_t)b * 3 * NPTS;  // targets

    __shared__ float s_y0[TCHUNK], s_y1[TCHUNK], s_y2[TCHUNK], s_nh[TCHUNK];
    __shared__ float wsum[THREADS / 32];
    __shared__ unsigned s_flag;

    const int tid = threadIdx.x;

    // ---- stage target chunk SoA: y0, y1, y2, nh = -0.5*||y||^2 ----
    const int tbase = tc * TCHUNK;
    #pragma unroll
    for (int i = tid; i < TCHUNK; i += THREADS) {
        float y0 = Y[tbase + i];
        float y1 = Y[NPTS + tbase + i];
        float y2 = Y[2 * NPTS + tbase + i];
        s_y0[i] = y0;
        s_y1[i] = y1;
        s_y2[i] = y2;
        s_nh[i] = -0.5f * (y0 * y0 + y1 * y1 + y2 * y2);
    }

    // ---- QPT queries per thread: packed broadcast registers ----
    const int qbase = qt * QTILE;
    u64 xp0[QPT], xp1[QPT], xp2[QPT];
    float hx[QPT];
    #pragma unroll
    for (int q = 0; q < QPT; q++) {
        int n = qbase + q * THREADS + tid;
        float x0 = X[n];
        float x1 = X[NPTS + n];
        float x2 = X[2 * NPTS + n];
        xp0[q] = pack2(x0);
        xp1[q] = pack2(x1);
        xp2[q] = pack2(x2);
        hx[q] = 0.5f * (x0 * x0 + x1 * x1 + x2 * x2);
    }
    __syncthreads();

    const unsigned a0 = (unsigned)__cvta_generic_to_shared(s_y0);
    const unsigned a1 = (unsigned)__cvta_generic_to_shared(s_y1);
    const unsigned a2 = (unsigned)__cvta_generic_to_shared(s_y2);
    const unsigned ah = (unsigned)__cvta_generic_to_shared(s_nh);

    float m0[QPT], m1[QPT];
    #pragma unroll
    for (int q = 0; q < QPT; q++) { m0[q] = NEG_INF; m1[q] = NEG_INF; }

    // ---- main loop: 4 targets/iter (broadcast LDS), 4 queries/thread ----
    #pragma unroll 4
    for (int j = 0; j < TCHUNK / 4; j++) {
        u64 A0, A1, B0, B1, C0, C1, H0, H1;
        const unsigned off = j * 16;
        lds_v2u64(a0 + off, A0, A1);   // y0[4j..4j+3] as two packed pairs
        lds_v2u64(a1 + off, B0, B1);
        lds_v2u64(a2 + off, C0, C1);
        lds_v2u64(ah + off, H0, H1);

        #pragma unroll
        for (int q = 0; q < QPT; q++) {
            u64 t0 = fma2(xp2[q], C0, H0);
            u64 t1 = fma2(xp2[q], C1, H1);
            t0 = fma2(xp1[q], B0, t0);
            t1 = fma2(xp1[q], B1, t1);
            t0 = fma2(xp0[q], A0, t0);
            t1 = fma2(xp0[q], A1, t1);
            float l0, h0, l1, h1;
            unpack2(t0, l0, h0);
            unpack2(t1, l1, h1);
            m0[q] = fmaxf(m0[q], l0);
            m1[q] = fmaxf(m1[q], h0);
            m0[q] = fmaxf(m0[q], l1);
            m1[q] = fmaxf(m1[q], h1);
        }
    }

    // ---- epilogue: t_full = max - hx <= 0, merge via raw-bit umin ----
    const int key0 = (dir * NBATCH + b) * NPTS + qbase + tid;
    #pragma unroll
    for (int q = 0; q < QPT; q++) {
        float tf = fmaxf(m0[q], m1[q]) - hx[q];
        atomicMin(&g_key[key0 + q * THREADS], __float_as_uint(tf));
    }

    // ---- last block performs the final sum (fused reduce) ----
    __threadfence();
    if (tid == 0)
        s_flag = (atomicAdd(&g_count, 1u) == (unsigned)(NBLOCKS - 1)) ? 1u : 0u;
    __syncthreads();
    if (s_flag) {
        const uint4* kp = (const uint4*)g_key;
        float sa = 0.0f, sb = 0.0f, sc = 0.0f, sd = 0.0f;
        for (int i = tid; i < NKEYS / 4; i += THREADS) {
            uint4 v = __ldcg(&kp[i]);
            sa += __uint_as_float(v.x);
            sb += __uint_as_float(v.y);
            sc += __uint_as_float(v.z);
            sd += __uint_as_float(v.w);
        }
        float s = (sa + sb) + (sc + sd);
        #pragma unroll
        for (int off = 16; off > 0; off >>= 1)
            s += __shfl_xor_sync(0xffffffffu, s, off);
        if ((tid & 31) == 0) wsum[tid >> 5] = s;
        __syncthreads();
        if (tid == 0) {
            float t = 0.0f;
            #pragma unroll
            for (int i = 0; i < THREADS / 32; i++) t += wsum[i];
            // min dist per query = -2 * t_full; two means each over B*NPTS
            out[0] = t * (-2.0f / (float)(NBATCH * NPTS));
        }
    }
}

extern "C" void kernel_launch(void* const* d_in, const int* in_sizes, int n_in,
                              void* d_out, int out_size) {
    const float* pred = (const float*)d_in[0];
    const float* targ = (const float*)d_in[1];
    float* out = (float*)d_out;

    chamfer_init_kernel<<<NKEYS / 1024, 1024>>>();
    chamfer_main_kernel<<<NBLOCKS, THREADS>>>(pred, targ, out);
}

// round 10
// speedup vs baseline: 1.0996x; 1.0996x over previous
#include <cuda_runtime.h>
#include <cuda_bf16.h>

// ChamferDistance: B=4, C=3, N=M=8192, fp32 -> scalar.
// t = x.y - 0.5||y||^2; per-query max; t_full = max - hx <= 0 -> raw-bit atomicMin.
// R10: snake partition. G=444 blocks (3 CTAs/SM x 148) each own a contiguous
//      range of the 65536 global j-iterations (32 super-units x 2048 iters).
//      Single wave, +-1 iter balance, ~148 iters/block amortizing prologue.
//      Inner engine = R6's (256 thr, QPT=8, 84% measured issue efficiency).

#define NPTS     8192
#define NBATCH   4
#define THREADS  256
#define QPT      8
#define QTILE    (THREADS * QPT)       // 2048 queries per super-unit
#define NQT      (NPTS / QTILE)        // 4
#define NSU      (2 * NBATCH * NQT)    // 32 super-units (dir,b,qt)
#define ITERS_SU 2048                  // 8192 targets / 4 per iter
#define TOT_IT   (NSU * ITERS_SU)      // 65536
#define G        444                   // grid size = 3 * 148
#define TCHUNK   256                   // staged targets per chunk
#define NKEYS    (2 * NBATCH * NPTS)   // 65536
#define NEG_INF  (-3.402823466e38f)

__device__ unsigned g_key[NKEYS];   // raw bits of t_full (<=0), merged via umin
__device__ unsigned g_count;

typedef unsigned long long u64;

__device__ __forceinline__ u64 fma2(u64 a, u64 b, u64 c) {
    u64 d;
    asm("fma.rn.f32x2 %0, %1, %2, %3;" : "=l"(d) : "l"(a), "l"(b), "l"(c));
    return d;
}
__device__ __forceinline__ u64 pack2(float x) {
    u64 d;
    asm("mov.b64 %0, {%1, %1};" : "=l"(d) : "f"(x));
    return d;
}
__device__ __forceinline__ void unpack2(u64 v, float& lo, float& hi) {
    asm("mov.b64 {%0, %1}, %2;" : "=f"(lo), "=f"(hi) : "l"(v));
}
__device__ __forceinline__ void lds_v2u64(unsigned addr, u64& a, u64& b) {
    asm volatile("ld.shared.v2.u64 {%0, %1}, [%2];" : "=l"(a), "=l"(b) : "r"(addr));
}

__global__ void chamfer_init_kernel() {
    int i = blockIdx.x * blockDim.x + threadIdx.x;
    g_key[i] = 0xFFFFFFFFu;   // umin identity
    if (i == 0) g_count = 0u;
}

__global__ __launch_bounds__(THREADS, 3)
void chamfer_main_kernel(const float* __restrict__ pred,
                         const float* __restrict__ targ,
                         float* __restrict__ out) {
    const int tid = threadIdx.x;

    __shared__ float s_y0[TCHUNK], s_y1[TCHUNK], s_y2[TCHUNK], s_nh[TCHUNK];
    __shared__ float wsum[THREADS / 32];
    __shared__ unsigned s_flag;

    int it            = (int)(((long long)blockIdx.x * TOT_IT) / G);
    const int it_last = (int)(((long long)(blockIdx.x + 1) * TOT_IT) / G);

    while (it < it_last) {
        const int su   = it >> 11;                          // / ITERS_SU
        const int sEnd = min(it_last, (su + 1) << 11);
        const int dir  = su >> 4;
        const int b    = (su >> 2) & 3;
        const int qt   = su & 3;

        const float* __restrict__ X = (dir ? targ : pred) + (size_t)b * 3 * NPTS;
        const float* __restrict__ Y = (dir ? pred : targ) + (size_t)b * 3 * NPTS;

        // ---- queries for this super-unit: packed broadcast registers ----
        const int qbase = qt * QTILE;
        u64 xp0[QPT], xp1[QPT], xp2[QPT];
        float hx[QPT];
        #pragma unroll
        for (int q = 0; q < QPT; q++) {
            int n = qbase + q * THREADS + tid;
            float x0 = X[n];
            float x1 = X[NPTS + n];
            float x2 = X[2 * NPTS + n];
            xp0[q] = pack2(x0);
            xp1[q] = pack2(x1);
            xp2[q] = pack2(x2);
            hx[q] = 0.5f * (x0 * x0 + x1 * x1 + x2 * x2);
        }

        float m0[QPT], m1[QPT];
        #pragma unroll
        for (int q = 0; q < QPT; q++) { m0[q] = NEG_INF; m1[q] = NEG_INF; }

        const unsigned a0 = (unsigned)__cvta_generic_to_shared(s_y0);
        const unsigned a1 = (unsigned)__cvta_generic_to_shared(s_y1);
        const unsigned a2 = (unsigned)__cvta_generic_to_shared(s_y2);
        const unsigned ah = (unsigned)__cvta_generic_to_shared(s_nh);

        // ---- target range of this segment (4 targets per iter) ----
        int       t    = (it   - (su << 11)) << 2;
        const int tEnd = (sEnd - (su << 11)) << 2;

        for (; t < tEnd; t += TCHUNK) {
            const int cnt = min(TCHUNK, tEnd - t);
            __syncthreads();
            for (int i = tid; i < cnt; i += THREADS) {
                float y0 = Y[t + i];
                float y1 = Y[NPTS + t + i];
                float y2 = Y[2 * NPTS + t + i];
                s_y0[i] = y0;
                s_y1[i] = y1;
                s_y2[i] = y2;
                s_nh[i] = -0.5f * (y0 * y0 + y1 * y1 + y2 * y2);
            }
            __syncthreads();

            const int nj = cnt >> 2;
            #pragma unroll 2
            for (int j = 0; j < nj; j++) {
                u64 A0, A1, B0, B1, C0, C1, H0, H1;
                const unsigned off = j * 16;
                lds_v2u64(a0 + off, A0, A1);
                lds_v2u64(a1 + off, B0, B1);
                lds_v2u64(a2 + off, C0, C1);
                lds_v2u64(ah + off, H0, H1);

                #pragma unroll
                for (int q = 0; q < QPT; q++) {
                    u64 t0 = fma2(xp2[q], C0, H0);
                    u64 t1 = fma2(xp2[q], C1, H1);
                    t0 = fma2(xp1[q], B0, t0);
                    t1 = fma2(xp1[q], B1, t1);
                    t0 = fma2(xp0[q], A0, t0);
                    t1 = fma2(xp0[q], A1, t1);
                    float l0, h0, l1, h1;
                    unpack2(t0, l0, h0);
                    unpack2(t1, l1, h1);
                    m0[q] = fmaxf(m0[q], l0);
                    m1[q] = fmaxf(m1[q], h0);
                    m0[q] = fmaxf(m0[q], l1);
                    m1[q] = fmaxf(m1[q], h1);
                }
            }
        }

        // ---- segment epilogue: merge partial maxes for this super-unit ----
        const int key0 = (dir * NBATCH + b) * NPTS + qbase + tid;
        #pragma unroll
        for (int q = 0; q < QPT; q++) {
            float tf = fmaxf(m0[q], m1[q]) - hx[q];
            atomicMin(&g_key[key0 + q * THREADS], __float_as_uint(tf));
        }

        it = sEnd;
    }

    // ---- last block performs the final sum ----
    __threadfence();
    __syncthreads();   // all threads' atomics fenced before the count bump
    if (tid == 0)
        s_flag = (atomicAdd(&g_count, 1u) == (unsigned)(G - 1)) ? 1u : 0u;
    __syncthreads();
    if (s_flag) {
        const uint4* kp = (const uint4*)g_key;
        float sa = 0.0f, sb = 0.0f, sc = 0.0f, sd = 0.0f;
        for (int i = tid; i < NKEYS / 4; i += THREADS) {
            uint4 v = __ldcg(&kp[i]);
            sa += __uint_as_float(v.x);
            sb += __uint_as_float(v.y);
            sc += __uint_as_float(v.z);
            sd += __uint_as_float(v.w);
        }
        float s = (sa + sb) + (sc + sd);
        #pragma unroll
        for (int off = 16; off > 0; off >>= 1)
            s += __shfl_xor_sync(0xffffffffu, s, off);
        if ((tid & 31) == 0) wsum[tid >> 5] = s;
        __syncthreads();
        if (tid == 0) {
            float tsum = 0.0f;
            #pragma unroll
            for (int i = 0; i < THREADS / 32; i++) tsum += wsum[i];
            // min dist per query = -2 * t_full; two means each over B*NPTS
            out[0] = tsum * (-2.0f / (float)(NBATCH * NPTS));
        }
    }
}

extern "C" void kernel_launch(void* const* d_in, const int* in_sizes, int n_in,
                              void* d_out, int out_size) {
    const float* pred = (const float*)d_in[0];
    const float* targ = (const float*)d_in[1];
    float* out = (float*)d_out;

    chamfer_init_kernel<<<NKEYS / 1024, 1024>>>();
    chamfer_main_kernel<<<G, THREADS>>>(pred, targ, out);
}